// round 7
// baseline (speedup 1.0000x reference)
#include <cuda_runtime.h>

// ReadGate, split-2 over M with fused split-K fixup:
//  grid (B, 2): each CTA streams half of memory[b], writes unnormalized partial
//  pooled + expsum to scratch; the LAST-arriving CTA per row (atomic counter)
//  combines both halves, normalizes, and applies out = pooled @ oW.T + ob.
//  No separate combine kernel.

constexpr int Bn = 2048;
constexpr int Mn = 2048;
constexpr int Dn = 64;
constexpr int Vn = 64;
constexpr int THREADS = 256;
constexpr int NHW = 16;                        // half-warps per CTA
constexpr int UNROLL = 4;                      // m-rows per half-warp per iter
constexpr int SPLIT = 2;
constexpr int MCHUNK = Mn / SPLIT;             // 1024
constexpr int ITERS = MCHUNK / (NHW * UNROLL); // 16

__device__ float g_pooled[Bn * SPLIT * Dn];    // unnormalized partial pooled
__device__ float g_sum[Bn * SPLIT];            // partial exp-sums
__device__ int   g_count[Bn];                  // arrival counters (monotonic; %SPLIT elects last)

__global__ __launch_bounds__(THREADS, 4)
void stream_kernel(const int* __restrict__ query,
                   const float* __restrict__ memory,
                   const float* __restrict__ emb,
                   const float* __restrict__ qW,
                   const float* __restrict__ qb,
                   const float* __restrict__ oW,
                   const float* __restrict__ ob,
                   float* __restrict__ out)
{
    __shared__ float w_sh[Dn * 65];            // qW staged, later oW in fixup
    __shared__ float e_sh[Dn];
    __shared__ float q_sh[Dn];                 // q vector, later normalized pooled
    __shared__ float pooled_sh[NHW][Dn];
    __shared__ float sum_sh[NHW];
    __shared__ int   last_sh;

    const int b   = blockIdx.x;
    const int s   = blockIdx.y;
    const int tid = threadIdx.x;
    const int hw   = tid >> 4;
    const int lane = tid & 15;

    const float4* __restrict__ mrow =
        reinterpret_cast<const float4*>(memory + (size_t)b * (Mn * Dn)
                                               + (size_t)s * (MCHUNK * Dn)) + lane;

    // ---- issue first tile loads IMMEDIATELY (independent of q) ----
    float4 v[UNROLL];
    #pragma unroll
    for (int j = 0; j < UNROLL; ++j)
        v[j] = __ldcs(mrow + (size_t)(hw + j * NHW) * (Dn / 4));

    // ---- prologue overlapped with loads in flight ----
    #pragma unroll
    for (int i = tid; i < Dn * Dn; i += THREADS)
        w_sh[(i >> 6) * 65 + (i & 63)] = qW[i];
    if (tid < Dn)
        e_sh[tid] = emb[query[b] * Dn + tid];
    __syncthreads();

    if (tid < Dn) {
        float acc = qb[tid];
        #pragma unroll
        for (int k = 0; k < Dn; ++k)
            acc = fmaf(e_sh[k], w_sh[tid * 65 + k], acc);
        q_sh[tid] = acc;
    }
    __syncthreads();

    const float q0 = q_sh[lane * 4 + 0];
    const float q1 = q_sh[lane * 4 + 1];
    const float q2 = q_sh[lane * 4 + 2];
    const float q3 = q_sh[lane * 4 + 3];

    float rsum = 0.f;
    float a0 = 0.f, a1 = 0.f, a2 = 0.f, a3 = 0.f;

    #pragma unroll 1
    for (int it = 0; it < ITERS; ++it) {
        // prefetch next iteration, clamped (last iter re-fetches L2-hot tile)
        const int nit = (it + 1 < ITERS) ? (it + 1) : (ITERS - 1);
        float4 nv[UNROLL];
        #pragma unroll
        for (int j = 0; j < UNROLL; ++j)
            nv[j] = __ldcs(mrow + (size_t)(hw + nit * (NHW * UNROLL) + j * NHW) * (Dn / 4));

        #pragma unroll
        for (int j = 0; j < UNROLL; ++j) {
            float sv = fmaf(v[j].x, q0, fmaf(v[j].y, q1, fmaf(v[j].z, q2, v[j].w * q3)));
            sv += __shfl_xor_sync(0xffffffffu, sv, 8);
            sv += __shfl_xor_sync(0xffffffffu, sv, 4);
            sv += __shfl_xor_sync(0xffffffffu, sv, 2);
            sv += __shfl_xor_sync(0xffffffffu, sv, 1);
            const float p = __expf(sv * 0.125f);   // no max-subtraction: |s/8| <~ 5
            rsum += p;
            a0 = fmaf(p, v[j].x, a0);
            a1 = fmaf(p, v[j].y, a1);
            a2 = fmaf(p, v[j].z, a2);
            a3 = fmaf(p, v[j].w, a3);
        }

        #pragma unroll
        for (int j = 0; j < UNROLL; ++j) v[j] = nv[j];
    }

    pooled_sh[hw][lane * 4 + 0] = a0;
    pooled_sh[hw][lane * 4 + 1] = a1;
    pooled_sh[hw][lane * 4 + 2] = a2;
    pooled_sh[hw][lane * 4 + 3] = a3;
    if (lane == 0) sum_sh[hw] = rsum;
    __syncthreads();

    // ---- write this CTA's partials ----
    if (tid < Dn) {
        float pl = 0.f;
        #pragma unroll
        for (int p = 0; p < NHW; ++p) pl += pooled_sh[p][tid];
        g_pooled[((size_t)b * SPLIT + s) * Dn + tid] = pl;
    }
    if (tid == 0) {
        float gs = 0.f;
        #pragma unroll
        for (int p = 0; p < NHW; ++p) gs += sum_sh[p];
        g_sum[b * SPLIT + s] = gs;
    }

    // ---- split-K fixup election (threadFence-reduction pattern) ----
    __threadfence();
    __syncthreads();
    if (tid == 0) {
        int old = atomicAdd(&g_count[b], 1);
        last_sh = (((old + 1) % SPLIT) == 0);
    }
    __syncthreads();
    if (!last_sh) return;
    __threadfence();   // ensure peer partials are visible

    // ---- last CTA: combine, normalize, output projection ----
    #pragma unroll
    for (int i = tid; i < Dn * Dn; i += THREADS)
        w_sh[(i >> 6) * 65 + (i & 63)] = oW[i];
    if (tid < Dn) {
        float pl = g_pooled[((size_t)b * SPLIT + 0) * Dn + tid]
                 + g_pooled[((size_t)b * SPLIT + 1) * Dn + tid];
        float gs = g_sum[b * SPLIT + 0] + g_sum[b * SPLIT + 1];
        q_sh[tid] = pl / gs;
    }
    __syncthreads();

    if (tid < Vn) {
        float acc = ob[tid];
        #pragma unroll
        for (int d = 0; d < Dn; ++d)
            acc = fmaf(q_sh[d], w_sh[tid * 65 + d], acc);
        out[(size_t)b * Vn + tid] = acc;
    }
}

extern "C" void kernel_launch(void* const* d_in, const int* in_sizes, int n_in,
                              void* d_out, int out_size)
{
    const int*   query  = (const int*)  d_in[0];
    const float* memory = (const float*)d_in[1];
    const float* emb    = (const float*)d_in[2];
    const float* qW     = (const float*)d_in[3];
    const float* qb     = (const float*)d_in[4];
    const float* oW     = (const float*)d_in[5];
    const float* ob     = (const float*)d_in[6];
    float* out = (float*)d_out;

    stream_kernel<<<dim3(Bn, SPLIT), THREADS>>>(query, memory, emb, qW, qb, oW, ob, out);
}

// round 8
// speedup vs baseline: 1.0414x; 1.0414x over previous
#include <cuda_runtime.h>

// ReadGate, split-2 over M (kills wave-quantization tail) + PDL-overlapped combine:
//  k1 grid (B, 2): stream memory[b, half], no-max softmax partials -> scratch.
//  k2 (PDL): launches into k1's tail-wave idle slots, stages oW in smem while k1
//     drains, grid-dependency-syncs, then combines/normalizes/projects.

constexpr int Bn = 2048;
constexpr int Mn = 2048;
constexpr int Dn = 64;
constexpr int Vn = 64;
constexpr int THREADS = 256;
constexpr int NHW = 16;                        // half-warps per CTA
constexpr int UNROLL = 4;                      // m-rows per half-warp per iter
constexpr int SPLIT = 2;
constexpr int MCHUNK = Mn / SPLIT;             // 1024
constexpr int ITERS = MCHUNK / (NHW * UNROLL); // 16

__device__ float g_pooled[Bn * SPLIT * Dn];    // unnormalized partial pooled
__device__ float g_sum[Bn * SPLIT];            // partial exp-sums

__global__ __launch_bounds__(THREADS, 4)
void stream_kernel(const int* __restrict__ query,
                   const float* __restrict__ memory,
                   const float* __restrict__ emb,
                   const float* __restrict__ qW,
                   const float* __restrict__ qb)
{
    __shared__ float w_sh[Dn * 65];
    __shared__ float e_sh[Dn];
    __shared__ float q_sh[Dn];
    __shared__ float pooled_sh[NHW][Dn];
    __shared__ float sum_sh[NHW];

    const int b   = blockIdx.x;
    const int s   = blockIdx.y;
    const int tid = threadIdx.x;
    const int hw   = tid >> 4;
    const int lane = tid & 15;

    const float4* __restrict__ mrow =
        reinterpret_cast<const float4*>(memory + (size_t)b * (Mn * Dn)
                                               + (size_t)s * (MCHUNK * Dn)) + lane;

    // ---- issue first tile loads IMMEDIATELY (independent of q) ----
    float4 v[UNROLL];
    #pragma unroll
    for (int j = 0; j < UNROLL; ++j)
        v[j] = __ldcs(mrow + (size_t)(hw + j * NHW) * (Dn / 4));

    // ---- prologue overlapped with loads in flight: stage qW, compute q ----
    #pragma unroll
    for (int i = tid; i < Dn * Dn; i += THREADS)
        w_sh[(i >> 6) * 65 + (i & 63)] = qW[i];
    if (tid < Dn)
        e_sh[tid] = emb[query[b] * Dn + tid];
    __syncthreads();

    if (tid < Dn) {
        float acc = qb[tid];
        #pragma unroll
        for (int k = 0; k < Dn; ++k)
            acc = fmaf(e_sh[k], w_sh[tid * 65 + k], acc);
        q_sh[tid] = acc;
    }
    __syncthreads();

    const float q0 = q_sh[lane * 4 + 0];
    const float q1 = q_sh[lane * 4 + 1];
    const float q2 = q_sh[lane * 4 + 2];
    const float q3 = q_sh[lane * 4 + 3];

    float rsum = 0.f;
    float a0 = 0.f, a1 = 0.f, a2 = 0.f, a3 = 0.f;

    #pragma unroll 1
    for (int it = 0; it < ITERS; ++it) {
        // prefetch next iteration, clamped (last iter re-fetches L2-hot tile)
        const int nit = (it + 1 < ITERS) ? (it + 1) : (ITERS - 1);
        float4 nv[UNROLL];
        #pragma unroll
        for (int j = 0; j < UNROLL; ++j)
            nv[j] = __ldcs(mrow + (size_t)(hw + nit * (NHW * UNROLL) + j * NHW) * (Dn / 4));

        #pragma unroll
        for (int j = 0; j < UNROLL; ++j) {
            float sv = fmaf(v[j].x, q0, fmaf(v[j].y, q1, fmaf(v[j].z, q2, v[j].w * q3)));
            sv += __shfl_xor_sync(0xffffffffu, sv, 8);
            sv += __shfl_xor_sync(0xffffffffu, sv, 4);
            sv += __shfl_xor_sync(0xffffffffu, sv, 2);
            sv += __shfl_xor_sync(0xffffffffu, sv, 1);
            const float p = __expf(sv * 0.125f);   // no max-subtraction: |s/8| <~ 5
            rsum += p;
            a0 = fmaf(p, v[j].x, a0);
            a1 = fmaf(p, v[j].y, a1);
            a2 = fmaf(p, v[j].z, a2);
            a3 = fmaf(p, v[j].w, a3);
        }

        #pragma unroll
        for (int j = 0; j < UNROLL; ++j) v[j] = nv[j];
    }

    pooled_sh[hw][lane * 4 + 0] = a0;
    pooled_sh[hw][lane * 4 + 1] = a1;
    pooled_sh[hw][lane * 4 + 2] = a2;
    pooled_sh[hw][lane * 4 + 3] = a3;
    if (lane == 0) sum_sh[hw] = rsum;
    __syncthreads();

    if (tid < Dn) {
        float pl = 0.f;
        #pragma unroll
        for (int p = 0; p < NHW; ++p) pl += pooled_sh[p][tid];
        g_pooled[((size_t)b * SPLIT + s) * Dn + tid] = pl;
    }
    if (tid == 0) {
        float gs = 0.f;
        #pragma unroll
        for (int p = 0; p < NHW; ++p) gs += sum_sh[p];
        g_sum[b * SPLIT + s] = gs;
    }
}

// ---------------- combine + output projection (PDL) ----------------
constexpr int ROWS_PER_BLK = 4;   // 512 blocks

__global__ __launch_bounds__(THREADS)
void combine_kernel(const float* __restrict__ oW,
                    const float* __restrict__ ob,
                    float* __restrict__ out)
{
    __shared__ float w_sh[Dn * 65];
    __shared__ float p_sh[ROWS_PER_BLK][Dn];

    const int tid = threadIdx.x;
    const int r   = tid >> 6;       // row group 0..3
    const int vv  = tid & 63;       // output index
    const int b   = blockIdx.x * ROWS_PER_BLK + r;

    // stage oW coalesced, padded — independent of streamer output, runs in overlap
    #pragma unroll
    for (int i = tid; i < Dn * Dn; i += THREADS)
        w_sh[(i >> 6) * 65 + (i & 63)] = oW[i];
    const float obv = ob[vv];

    // wait for the streamer grid to complete before touching its partials
    cudaGridDependencySynchronize();

    float pl = g_pooled[((size_t)b * SPLIT + 0) * Dn + vv]
             + g_pooled[((size_t)b * SPLIT + 1) * Dn + vv];
    float gs = g_sum[b * SPLIT + 0] + g_sum[b * SPLIT + 1];
    p_sh[r][vv] = pl / gs;
    __syncthreads();

    float acc = obv;
    #pragma unroll
    for (int d = 0; d < Dn; ++d)
        acc = fmaf(p_sh[r][d], w_sh[vv * 65 + d], acc);
    out[(size_t)b * Vn + vv] = acc;
}

extern "C" void kernel_launch(void* const* d_in, const int* in_sizes, int n_in,
                              void* d_out, int out_size)
{
    const int*   query  = (const int*)  d_in[0];
    const float* memory = (const float*)d_in[1];
    const float* emb    = (const float*)d_in[2];
    const float* qW     = (const float*)d_in[3];
    const float* qb     = (const float*)d_in[4];
    const float* oW     = (const float*)d_in[5];
    const float* ob     = (const float*)d_in[6];
    float* out = (float*)d_out;

    stream_kernel<<<dim3(Bn, SPLIT), THREADS>>>(query, memory, emb, qW, qb);

    // PDL launch: combine may start in k1's tail idle slots; it grid-syncs
    // before reading k1's outputs.
    cudaLaunchConfig_t cfg = {};
    cfg.gridDim  = dim3(Bn / ROWS_PER_BLK);
    cfg.blockDim = dim3(THREADS);
    cudaLaunchAttribute attr[1];
    attr[0].id = cudaLaunchAttributeProgrammaticStreamSerialization;
    attr[0].val.programmaticStreamSerializationAllowed = 1;
    cfg.attrs = attr;
    cfg.numAttrs = 1;
    cudaLaunchKernelEx(&cfg, combine_kernel, oW, ob, out);
}